// round 3
// baseline (speedup 1.0000x reference)
#include <cuda_runtime.h>

#define BATCH 8
#define SEQ   2048
#define DM    1024
#define EDIM  64

// Scratch for projected q,k,v (allocation-free rule -> __device__ globals). 12 MB total.
__device__ float g_q[BATCH * SEQ * EDIM];
__device__ float g_k[BATCH * SEQ * EDIM];
__device__ float g_v[BATCH * SEQ * EDIM];

// ---------------------------------------------------------------------------
// Projection GEMM: out[16384,64] = X[16384,1024] @ W[1024,64] + b
// grid (256, 3): y selects q/k/v. 256 threads, 64-row x 64-col tile, 4x4 microtile.
// ---------------------------------------------------------------------------
__global__ void proj_kernel(const float* __restrict__ x,
                            const float* __restrict__ Wk, const float* __restrict__ bk,
                            const float* __restrict__ Wq, const float* __restrict__ bq,
                            const float* __restrict__ Wv, const float* __restrict__ bv)
{
    __shared__ float Xs[64 * 33];   // padded: conflict-free strided row reads
    __shared__ float Ws[32 * 64];

    const int mat = blockIdx.y;
    const float* __restrict__ W    = (mat == 0) ? Wq : (mat == 1) ? Wk : Wv;
    const float* __restrict__ bias = (mat == 0) ? bq : (mat == 1) ? bk : bv;
    float* __restrict__ outp       = (mat == 0) ? g_q : (mat == 1) ? g_k : g_v;
    const float scale = (mat == 0) ? 0.125f : 1.0f;   // fold 1/sqrt(64) into q

    const int rowbase = blockIdx.x * 64;
    const int tid = threadIdx.x;
    const int ty = tid >> 4;        // 0..15 -> rows ty*4 + r
    const int tx = tid & 15;        // cols tx + 16*cc

    float acc[4][4];
#pragma unroll
    for (int r = 0; r < 4; r++)
#pragma unroll
        for (int c = 0; c < 4; c++) acc[r][c] = 0.0f;

    for (int d0 = 0; d0 < DM; d0 += 32) {
        __syncthreads();
#pragma unroll
        for (int i = 0; i < 8; i++) {           // 64x32 X tile
            int idx = tid + i * 256;
            int row = idx >> 5, d = idx & 31;
            Xs[row * 33 + d] = x[(rowbase + row) * DM + d0 + d];
        }
#pragma unroll
        for (int i = 0; i < 8; i++) {           // 32x64 W tile
            int idx = tid + i * 256;
            int d = idx >> 6, col = idx & 63;
            Ws[idx] = W[(d0 + d) * 64 + col];
        }
        __syncthreads();

#pragma unroll 8
        for (int d = 0; d < 32; d++) {
            float xv[4], wv[4];
#pragma unroll
            for (int r = 0; r < 4; r++) xv[r] = Xs[(ty * 4 + r) * 33 + d];
#pragma unroll
            for (int c = 0; c < 4; c++) wv[c] = Ws[d * 64 + tx + 16 * c];
#pragma unroll
            for (int r = 0; r < 4; r++)
#pragma unroll
                for (int c = 0; c < 4; c++) acc[r][c] += xv[r] * wv[c];
        }
    }

#pragma unroll
    for (int r = 0; r < 4; r++) {
        int row = rowbase + ty * 4 + r;
#pragma unroll
        for (int c = 0; c < 4; c++) {
            int col = tx + 16 * c;
            outp[row * 64 + col] = (acc[r][c] + bias[col]) * scale;
        }
    }
}

// ---------------------------------------------------------------------------
// Fused causal attention + output projection.
// grid (64, 8): x = query tile (32 rows), y = batch. 256 threads.
// Online softmax over 64-wide key tiles; P staged through shared (aliases K).
// ---------------------------------------------------------------------------
__device__ __forceinline__ float red_max16(float v) {
#pragma unroll
    for (int o = 8; o > 0; o >>= 1) v = fmaxf(v, __shfl_xor_sync(0xffffffffu, v, o));
    return v;
}
__device__ __forceinline__ float red_sum16(float v) {
#pragma unroll
    for (int o = 8; o > 0; o >>= 1) v += __shfl_xor_sync(0xffffffffu, v, o);
    return v;
}

__global__ void attn_kernel(const float* __restrict__ W0,
                            const float* __restrict__ b0,
                            float* __restrict__ out)
{
    __shared__ float Qs[32 * 64];    // [row][d]
    __shared__ float KP[64 * 65];    // K tile [col][d] (pad 65), later P [row][col], later ctx
    __shared__ float VW[64 * 64];    // V tile [col][e], later W0 [e][o]

    const int b = blockIdx.y;
    const int qbase = blockIdx.x * 32;
    const int tid = threadIdx.x;
    const int ty = tid >> 4;         // 0..15 -> rows r0 = ty*2 (+1)
    const int tx = tid & 15;         // cols tx + 16*cc
    const int r0 = ty * 2;

    const float* __restrict__ qp = g_q + (b * SEQ + qbase) * EDIM;

#pragma unroll
    for (int i = 0; i < 8; i++) {    // 32x64 Q tile, contiguous
        int idx = tid + i * 256;
        Qs[idx] = qp[idx];
    }

    float acc[2][4];
#pragma unroll
    for (int r = 0; r < 2; r++)
#pragma unroll
        for (int c = 0; c < 4; c++) acc[r][c] = 0.0f;
    float m[2] = {-1e30f, -1e30f};
    float l[2] = {0.0f, 0.0f};

    const int kt_last = (qbase + 31) >> 6;
    for (int kt = 0; kt <= kt_last; kt++) {
        __syncthreads();             // prior P/V consumers done
        const float* __restrict__ kp = g_k + (b * SEQ + kt * 64) * EDIM;
        const float* __restrict__ vp = g_v + (b * SEQ + kt * 64) * EDIM;
#pragma unroll
        for (int i = 0; i < 16; i++) {   // 64x64 K and V tiles
            int idx = tid + i * 256;
            int row = idx >> 6, d = idx & 63;
            KP[row * 65 + d] = kp[idx];
            VW[idx] = vp[idx];
        }
        __syncthreads();

        // S = Q K^T  (scale already folded into q)
        float s[2][4];
#pragma unroll
        for (int r = 0; r < 2; r++)
#pragma unroll
            for (int c = 0; c < 4; c++) s[r][c] = 0.0f;

#pragma unroll 4
        for (int d = 0; d < 64; d++) {
            float q0 = Qs[r0 * 64 + d];
            float q1 = Qs[(r0 + 1) * 64 + d];
#pragma unroll
            for (int c = 0; c < 4; c++) {
                float kv = KP[(tx + 16 * c) * 65 + d];
                s[0][c] += q0 * kv;
                s[1][c] += q1 * kv;
            }
        }

        if (kt == kt_last) {         // causal mask only hits the diagonal tile
            int colb = kt * 64;
#pragma unroll
            for (int c = 0; c < 4; c++) {
                int col = colb + tx + 16 * c;
                if (col > qbase + r0)     s[0][c] = -1e30f;
                if (col > qbase + r0 + 1) s[1][c] = -1e30f;
            }
        }

        // Online softmax update
#pragma unroll
        for (int r = 0; r < 2; r++) {
            float tm = fmaxf(fmaxf(s[r][0], s[r][1]), fmaxf(s[r][2], s[r][3]));
            tm = red_max16(tm);
            float nm = fmaxf(m[r], tm);
            float corr = expf(m[r] - nm);
            float ts = 0.0f;
#pragma unroll
            for (int c = 0; c < 4; c++) {
                s[r][c] = expf(s[r][c] - nm);
                ts += s[r][c];
            }
            ts = red_sum16(ts);
            l[r] = l[r] * corr + ts;
#pragma unroll
            for (int c = 0; c < 4; c++) acc[r][c] *= corr;
            m[r] = nm;
        }

        __syncthreads();             // everyone done reading K
#pragma unroll
        for (int c = 0; c < 4; c++) {   // P -> shared (row-major, pad 65)
            KP[r0 * 65 + tx + 16 * c]       = s[0][c];
            KP[(r0 + 1) * 65 + tx + 16 * c] = s[1][c];
        }
        __syncthreads();

        // acc += P @ V
#pragma unroll 4
        for (int c = 0; c < 64; c++) {
            float p0 = KP[r0 * 65 + c];
            float p1 = KP[(r0 + 1) * 65 + c];
#pragma unroll
            for (int e = 0; e < 4; e++) {
                float vv = VW[c * 64 + tx + 16 * e];
                acc[0][e] += p0 * vv;
                acc[1][e] += p1 * vv;
            }
        }
    }

    // Epilogue: ctx = acc / l, then out = ctx @ W0 + b0
    __syncthreads();
    float inv0 = 1.0f / l[0], inv1 = 1.0f / l[1];
#pragma unroll
    for (int c = 0; c < 4; c++) {
        KP[r0 * 65 + tx + 16 * c]       = acc[0][c] * inv0;
        KP[(r0 + 1) * 65 + tx + 16 * c] = acc[1][c] * inv1;
    }
#pragma unroll
    for (int i = 0; i < 16; i++) {   // W0 [64][64] -> shared
        int idx = tid + i * 256;
        VW[idx] = W0[idx];
    }
    __syncthreads();

    float o0[4] = {0, 0, 0, 0}, o1[4] = {0, 0, 0, 0};
#pragma unroll 4
    for (int e = 0; e < 64; e++) {
        float c0 = KP[r0 * 65 + e];
        float c1 = KP[(r0 + 1) * 65 + e];
#pragma unroll
        for (int c = 0; c < 4; c++) {
            float w = VW[e * 64 + tx + 16 * c];
            o0[c] += c0 * w;
            o1[c] += c1 * w;
        }
    }

#pragma unroll
    for (int c = 0; c < 4; c++) {
        int col = tx + 16 * c;
        float bb = b0[col];
        out[(b * SEQ + qbase + r0) * 64 + col]     = o0[c] + bb;
        out[(b * SEQ + qbase + r0 + 1) * 64 + col] = o1[c] + bb;
    }
}

extern "C" void kernel_launch(void* const* d_in, const int* in_sizes, int n_in,
                              void* d_out, int out_size)
{
    const float* x  = (const float*)d_in[0];
    const float* Wk = (const float*)d_in[1];
    const float* bk = (const float*)d_in[2];
    const float* Wq = (const float*)d_in[3];
    const float* bq = (const float*)d_in[4];
    const float* Wv = (const float*)d_in[5];
    const float* bv = (const float*)d_in[6];
    const float* W0 = (const float*)d_in[7];
    const float* b0 = (const float*)d_in[8];
    float* out = (float*)d_out;

    dim3 gproj(256, 3);
    proj_kernel<<<gproj, 256>>>(x, Wk, bk, Wq, bq, Wv, bv);

    dim3 gattn(64, BATCH);
    attn_kernel<<<gattn, 256>>>(W0, b0, out);
}

// round 5
// speedup vs baseline: 2.6735x; 2.6735x over previous
#include <cuda_runtime.h>
#include <cuda_bf16.h>
#include <cstdint>

#define BATCH 8
#define SEQ   2048
#define DM    1024
#define ED    64

// ---------------- device scratch (allocation-free rule) ----------------
__device__ __nv_bfloat16 g_qh[BATCH*SEQ*ED], g_ql[BATCH*SEQ*ED];
__device__ __nv_bfloat16 g_kh[BATCH*SEQ*ED], g_kl[BATCH*SEQ*ED];
__device__ __nv_bfloat16 g_vth[BATCH*ED*SEQ], g_vtl[BATCH*ED*SEQ];   // V transposed [b][e][t]
__device__ __nv_bfloat16 g_wth[3*ED*DM],  g_wtl[3*ED*DM];            // W^T [mat][n][d]

// ---------------- helpers ----------------
__device__ __forceinline__ uint32_t smem_u32(const void* p) {
    uint32_t a;
    asm("{ .reg .u64 t; cvta.to.shared.u64 t, %1; cvt.u32.u64 %0, t; }" : "=r"(a) : "l"(p));
    return a;
}

__device__ __forceinline__ void ldmA(uint32_t* a, uint32_t addr) {
    asm volatile("ldmatrix.sync.aligned.m8n8.x4.shared.b16 {%0,%1,%2,%3}, [%4];"
        : "=r"(a[0]), "=r"(a[1]), "=r"(a[2]), "=r"(a[3]) : "r"(addr));
}
__device__ __forceinline__ void ldmB(uint32_t* b, uint32_t addr) {
    asm volatile("ldmatrix.sync.aligned.m8n8.x2.shared.b16 {%0,%1}, [%2];"
        : "=r"(b[0]), "=r"(b[1]) : "r"(addr));
}
__device__ __forceinline__ void mmaf(float* d, const uint32_t* a, const uint32_t* b) {
    asm volatile("mma.sync.aligned.m16n8k16.row.col.f32.bf16.bf16.f32 "
        "{%0,%1,%2,%3}, {%4,%5,%6,%7}, {%8,%9}, {%0,%1,%2,%3};"
        : "+f"(d[0]), "+f"(d[1]), "+f"(d[2]), "+f"(d[3])
        : "r"(a[0]), "r"(a[1]), "r"(a[2]), "r"(a[3]), "r"(b[0]), "r"(b[1]));
}

union U4 { uint4 u; __nv_bfloat16 h[8]; };
union U2 { uint2 u; __nv_bfloat16 h[4]; };
union UB2 { uint32_t u; __nv_bfloat16 h[2]; };

__device__ __forceinline__ void split2(float f, __nv_bfloat16& hi, __nv_bfloat16& lo) {
    hi = __float2bfloat16(f);
    lo = __float2bfloat16(f - __bfloat162float(hi));
}
__device__ __forceinline__ uint32_t packbf(__nv_bfloat16 a, __nv_bfloat16 b) {
    UB2 u; u.h[0] = a; u.h[1] = b; return u.u;
}

// ---------------------------------------------------------------------------
// Kernel 0: weights -> transposed bf16 hi/lo.
// ---------------------------------------------------------------------------
__global__ void prep_kernel(const float* __restrict__ Wq, const float* __restrict__ Wk,
                            const float* __restrict__ Wv)
{
    int tid = blockIdx.x * 256 + threadIdx.x;
    for (int i = tid; i < 3 * ED * DM; i += 96 * 256) {
        int mat = i >> 16, rem = i & 65535;
        int n = rem >> 10, d = rem & 1023;
        const float* W = (mat == 0) ? Wq : (mat == 1) ? Wk : Wv;
        __nv_bfloat16 h, l;
        split2(W[d * ED + n], h, l);
        g_wth[i] = h; g_wtl[i] = l;
    }
}

// ---------------------------------------------------------------------------
// Kernel 1: QKV projection via mma.sync bf16x3.
// grid (128, 3) x 256 thr. CTA tile 128x64, warp tile 32x32.
// SMEM: bias@0 XH@512 XL@18944 WH@37376 WL@46592. stride 144B. 55808 B.
// ---------------------------------------------------------------------------
#define PJ_XH 512
#define PJ_XL 18944
#define PJ_WH 37376
#define PJ_WL 46592
#define PJ_SMEM 55808

__global__ void __launch_bounds__(256, 1)
proj_kernel(const float* __restrict__ x, const float* __restrict__ bq,
            const float* __restrict__ bk, const float* __restrict__ bv)
{
    extern __shared__ char smem[];
    const uint32_t sb = smem_u32(smem);
    const int tid = threadIdx.x, lane = tid & 31, wid = tid >> 5;
    const int mw = wid >> 1, nh = wid & 1;
    const int g = lane >> 2, tq = lane & 3;
    const int mat = blockIdx.y;
    const int rowbase = blockIdx.x * 128;
    const float* bias = (mat == 0) ? bq : (mat == 1) ? bk : bv;
    if (tid < 64) ((float*)smem)[tid] = bias[tid];

    const __nv_bfloat16* wh = g_wth + (size_t)mat * ED * DM;
    const __nv_bfloat16* wl = g_wtl + (size_t)mat * ED * DM;

    float acc[2][4][4];
#pragma unroll
    for (int a = 0; a < 2; a++)
#pragma unroll
        for (int bb = 0; bb < 4; bb++)
#pragma unroll
            for (int c = 0; c < 4; c++) acc[a][bb][c] = 0.0f;

    for (int k0 = 0; k0 < DM; k0 += 64) {
        __syncthreads();
#pragma unroll
        for (int i = 0; i < 8; i++) {                    // X tile 128x64 fp32 -> hi/lo
            int idx = i * 256 + tid;
            int r = idx >> 4, jj = idx & 15;
            float4 v = __ldg((const float4*)(x + (size_t)(rowbase + r) * DM + k0) + jj);
            U2 h, l;
            split2(v.x, h.h[0], l.h[0]); split2(v.y, h.h[1], l.h[1]);
            split2(v.z, h.h[2], l.h[2]); split2(v.w, h.h[3], l.h[3]);
            *(uint2*)(smem + PJ_XH + r * 144 + jj * 8) = h.u;
            *(uint2*)(smem + PJ_XL + r * 144 + jj * 8) = l.u;
        }
#pragma unroll
        for (int i = 0; i < 4; i++) {                    // W tiles 64x64 hi+lo
            int idx = i * 256 + tid;
            int part = idx >> 9, rem = idx & 511;
            int r = rem >> 3, jj = rem & 7;
            const __nv_bfloat16* src = (part ? wl : wh) + (size_t)r * DM + k0;
            uint4 v = __ldg((const uint4*)src + jj);
            *(uint4*)(smem + (part ? PJ_WL : PJ_WH) + r * 144 + jj * 16) = v;
        }
        __syncthreads();

#pragma unroll
        for (int kc = 0; kc < 4; kc++) {
            uint32_t ah[2][4], al[2][4];
#pragma unroll
            for (int mi = 0; mi < 2; mi++) {
                uint32_t ao = (uint32_t)(mw * 32 + mi * 16 + (lane & 15)) * 144 + kc * 32 + (lane >> 4) * 16;
                ldmA(ah[mi], sb + PJ_XH + ao);
                ldmA(al[mi], sb + PJ_XL + ao);
            }
#pragma unroll
            for (int ni = 0; ni < 4; ni++) {
                uint32_t bo = (uint32_t)(nh * 32 + ni * 8 + (lane & 7)) * 144 + kc * 32 + ((lane >> 3) & 1) * 16;
                uint32_t bh[2], bl[2];
                ldmB(bh, sb + PJ_WH + bo);
                ldmB(bl, sb + PJ_WL + bo);
#pragma unroll
                for (int mi = 0; mi < 2; mi++) {
                    mmaf(acc[mi][ni], ah[mi], bh);
                    mmaf(acc[mi][ni], ah[mi], bl);
                    mmaf(acc[mi][ni], al[mi], bh);
                }
            }
        }
    }

    // epilogue: fragments -> staged smem [128][65] -> coalesced hi/lo global stores
    __syncthreads();
    const float scale = (mat == 0) ? 0.125f : 1.0f;      // fold 1/sqrt(64) into q
    const float* bs = (const float*)smem;
    float* stg = (float*)(smem + 512);
#pragma unroll
    for (int mi = 0; mi < 2; mi++)
#pragma unroll
        for (int ni = 0; ni < 4; ni++)
#pragma unroll
            for (int j = 0; j < 4; j++) {
                int row = mw * 32 + mi * 16 + (j >> 1) * 8 + g;
                int col = nh * 32 + ni * 8 + tq * 2 + (j & 1);
                stg[row * 65 + col] = (acc[mi][ni][j] + bs[col]) * scale;
            }
    __syncthreads();

    if (mat < 2) {
        int r = tid >> 1, half = tid & 1;
        U4 hb[4], lb[4];
#pragma unroll
        for (int i = 0; i < 32; i++) {
            split2(stg[r * 65 + half * 32 + i], hb[i >> 3].h[i & 7], lb[i >> 3].h[i & 7]);
        }
        __nv_bfloat16* dh = ((mat == 0) ? g_qh : g_kh) + (size_t)(rowbase + r) * ED + half * 32;
        __nv_bfloat16* dl = ((mat == 0) ? g_ql : g_kl) + (size_t)(rowbase + r) * ED + half * 32;
#pragma unroll
        for (int i = 0; i < 4; i++) { ((uint4*)dh)[i] = hb[i].u; ((uint4*)dl)[i] = lb[i].u; }
    } else {
        int e = tid >> 2, qq = tid & 3;
        int b = rowbase >> 11, tb = (rowbase & 2047) + qq * 32;
        U4 hb[4], lb[4];
#pragma unroll
        for (int i = 0; i < 32; i++) {
            split2(stg[(qq * 32 + i) * 65 + e], hb[i >> 3].h[i & 7], lb[i >> 3].h[i & 7]);
        }
        __nv_bfloat16* dh = g_vth + (size_t)(b * ED + e) * SEQ + tb;
        __nv_bfloat16* dl = g_vtl + (size_t)(b * ED + e) * SEQ + tb;
#pragma unroll
        for (int i = 0; i < 4; i++) { ((uint4*)dh)[i] = hb[i].u; ((uint4*)dl)[i] = lb[i].u; }
    }
}

// ---------------------------------------------------------------------------
// Kernel 2: causal flash attention + output projection via mma.sync bf16x3.
// grid (16, 8) x 256 thr. 128 queries/CTA; 8 warps = 4M x 2N(key halves).
// SMEM: rmax@0 rsum@1024 b0@2048 QH@2560 QL@20992 KH@39424 KL@48640
//       VH@57856 VL@67072. stride 144B. total 76288 B.
// Epilogue reuse: ctxbuf[128][65]f32 @2560 (Q area), W0[64][64]f32 @39424 (K area).
// ---------------------------------------------------------------------------
#define AT_RMAX 0
#define AT_RSUM 1024
#define AT_B0   2048
#define AT_QH   2560
#define AT_QL   20992
#define AT_KH   39424
#define AT_KL   48640
#define AT_VH   57856
#define AT_VL   67072
#define AT_SMEM 76288
#define AT_CTX  2560
#define AT_W0   39424

__global__ void __launch_bounds__(256, 1)
attn_kernel(const float* __restrict__ W0, const float* __restrict__ b0,
            float* __restrict__ out)
{
    extern __shared__ char smem[];
    const uint32_t sb = smem_u32(smem);
    const int tid = threadIdx.x, lane = tid & 31, wid = tid >> 5;
    const int mw = wid >> 1, nh = wid & 1;
    const int g = lane >> 2, tq = lane & 3;
    const int b = blockIdx.y;
    const int qb = blockIdx.x * 128;

    if (tid < 64) ((float*)(smem + AT_B0))[tid] = b0[tid];

    // Q tile 128x64 hi+lo -> smem (persistent)
#pragma unroll
    for (int i = 0; i < 8; i++) {
        int idx = i * 256 + tid;
        int part = idx >> 10, rem = idx & 1023;
        int r = rem >> 3, jj = rem & 7;
        const __nv_bfloat16* src = (part ? g_ql : g_qh) + (size_t)(b * SEQ + qb + r) * ED;
        uint4 v = __ldg((const uint4*)src + jj);
        *(uint4*)(smem + (part ? AT_QL : AT_QH) + r * 144 + jj * 16) = v;
    }

    float ctx[2][8][4];
#pragma unroll
    for (int a = 0; a < 2; a++)
#pragma unroll
        for (int bb = 0; bb < 8; bb++)
#pragma unroll
            for (int c = 0; c < 4; c++) ctx[a][bb][c] = 0.0f;
    float mrow[2][2] = {{-1e30f, -1e30f}, {-1e30f, -1e30f}};
    float lrow[2][2] = {{0.0f, 0.0f}, {0.0f, 0.0f}};

    float* rmax = (float*)(smem + AT_RMAX);
    float* rsum = (float*)(smem + AT_RSUM);

    const int nt = blockIdx.x * 2 + 2;
    for (int t = 0; t < nt; t++) {
        __syncthreads();
#pragma unroll
        for (int i = 0; i < 8; i++) {                    // K,V tiles 4 x 64x64
            int idx = i * 256 + tid;
            int part = idx >> 9, rem = idx & 511;
            int r = rem >> 3, jj = rem & 7;
            const __nv_bfloat16* src;
            uint32_t doff;
            if (part == 0)      { src = g_kh  + (size_t)(b * SEQ + t * 64 + r) * ED; doff = AT_KH; }
            else if (part == 1) { src = g_kl  + (size_t)(b * SEQ + t * 64 + r) * ED; doff = AT_KL; }
            else if (part == 2) { src = g_vth + (size_t)(b * ED + r) * SEQ + t * 64; doff = AT_VH; }
            else                { src = g_vtl + (size_t)(b * ED + r) * SEQ + t * 64; doff = AT_VL; }
            uint4 v = __ldg((const uint4*)src + jj);
            *(uint4*)(smem + doff + r * 144 + jj * 16) = v;
        }
        __syncthreads();

        // S = Q K^T
        float s[2][4][4];
#pragma unroll
        for (int a = 0; a < 2; a++)
#pragma unroll
            for (int bb = 0; bb < 4; bb++)
#pragma unroll
                for (int c = 0; c < 4; c++) s[a][bb][c] = 0.0f;

#pragma unroll
        for (int kc = 0; kc < 4; kc++) {
            uint32_t ah[2][4], al[2][4];
#pragma unroll
            for (int mi = 0; mi < 2; mi++) {
                uint32_t ao = (uint32_t)(mw * 32 + mi * 16 + (lane & 15)) * 144 + kc * 32 + (lane >> 4) * 16;
                ldmA(ah[mi], sb + AT_QH + ao);
                ldmA(al[mi], sb + AT_QL + ao);
            }
#pragma unroll
            for (int ni = 0; ni < 4; ni++) {
                uint32_t bo = (uint32_t)(nh * 32 + ni * 8 + (lane & 7)) * 144 + kc * 32 + ((lane >> 3) & 1) * 16;
                uint32_t bh[2], bl[2];
                ldmB(bh, sb + AT_KH + bo);
                ldmB(bl, sb + AT_KL + bo);
#pragma unroll
                for (int mi = 0; mi < 2; mi++) {
                    mmaf(s[mi][ni], ah[mi], bh);
                    mmaf(s[mi][ni], ah[mi], bl);
                    mmaf(s[mi][ni], al[mi], bh);
                }
            }
        }

        if (t >= nt - 2) {                               // causal mask (diagonal tiles)
#pragma unroll
            for (int mi = 0; mi < 2; mi++)
#pragma unroll
                for (int ni = 0; ni < 4; ni++)
#pragma unroll
                    for (int j = 0; j < 4; j++) {
                        int row = qb + mw * 32 + mi * 16 + (j >> 1) * 8 + g;
                        int col = t * 64 + nh * 32 + ni * 8 + tq * 2 + (j & 1);
                        if (col > row) s[mi][ni][j] = -1e30f;
                    }
        }

        // online softmax: quad shuffle + cross-warp smem exchange
        float corr[2][2];
#pragma unroll
        for (int mi = 0; mi < 2; mi++)
#pragma unroll
            for (int rh = 0; rh < 2; rh++) {
                float mx = -1e30f;
#pragma unroll
                for (int ni = 0; ni < 4; ni++)
                    mx = fmaxf(mx, fmaxf(s[mi][ni][rh * 2], s[mi][ni][rh * 2 + 1]));
                mx = fmaxf(mx, __shfl_xor_sync(0xffffffffu, mx, 1));
                mx = fmaxf(mx, __shfl_xor_sync(0xffffffffu, mx, 2));
                if (tq == 0) rmax[(mw * 32 + mi * 16 + rh * 8 + g) * 2 + nh] = mx;
            }
        __syncthreads();
#pragma unroll
        for (int mi = 0; mi < 2; mi++)
#pragma unroll
            for (int rh = 0; rh < 2; rh++) {
                int row = mw * 32 + mi * 16 + rh * 8 + g;
                float tm = fmaxf(rmax[row * 2], rmax[row * 2 + 1]);
                float nm = fmaxf(mrow[mi][rh], tm);
                corr[mi][rh] = __expf(mrow[mi][rh] - nm);
                mrow[mi][rh] = nm;
                float sum = 0.0f;
#pragma unroll
                for (int ni = 0; ni < 4; ni++) {
                    float p0 = __expf(s[mi][ni][rh * 2] - nm);
                    float p1 = __expf(s[mi][ni][rh * 2 + 1] - nm);
                    s[mi][ni][rh * 2] = p0; s[mi][ni][rh * 2 + 1] = p1;
                    sum += p0 + p1;
                }
                sum += __shfl_xor_sync(0xffffffffu, sum, 1);
                sum += __shfl_xor_sync(0xffffffffu, sum, 2);
                if (tq == 0) rsum[row * 2 + nh] = sum;
            }
        __syncthreads();
#pragma unroll
        for (int mi = 0; mi < 2; mi++)
#pragma unroll
            for (int rh = 0; rh < 2; rh++) {
                int row = mw * 32 + mi * 16 + rh * 8 + g;
                lrow[mi][rh] = lrow[mi][rh] * corr[mi][rh] + rsum[row * 2] + rsum[row * 2 + 1];
            }
#pragma unroll
        for (int mi = 0; mi < 2; mi++)
#pragma unroll
            for (int ni = 0; ni < 8; ni++)
#pragma unroll
                for (int j = 0; j < 4; j++) ctx[mi][ni][j] *= corr[mi][j >> 1];

        // PV: P (regs, hi/lo) @ V (smem B-frags)
#pragma unroll
        for (int kc = 0; kc < 2; kc++) {
            uint32_t ph[2][4], pl[2][4];
#pragma unroll
            for (int mi = 0; mi < 2; mi++)
#pragma unroll
                for (int h2 = 0; h2 < 2; h2++)
#pragma unroll
                    for (int rh = 0; rh < 2; rh++) {
                        __nv_bfloat16 h0, l0, h1, l1;
                        split2(s[mi][2 * kc + h2][rh * 2],     h0, l0);
                        split2(s[mi][2 * kc + h2][rh * 2 + 1], h1, l1);
                        ph[mi][h2 * 2 + rh] = packbf(h0, h1);
                        pl[mi][h2 * 2 + rh] = packbf(l0, l1);
                    }
#pragma unroll
            for (int ni = 0; ni < 8; ni++) {
                uint32_t bo = (uint32_t)(ni * 8 + (lane & 7)) * 144 + (nh * 32 + kc * 16) * 2 + ((lane >> 3) & 1) * 16;
                uint32_t bh[2], bl[2];
                ldmB(bh, sb + AT_VH + bo);
                ldmB(bl, sb + AT_VL + bo);
#pragma unroll
                for (int mi = 0; mi < 2; mi++) {
                    mmaf(ctx[mi][ni], ph[mi], bh);
                    mmaf(ctx[mi][ni], ph[mi], bl);
                    mmaf(ctx[mi][ni], pl[mi], bh);
                }
            }
        }
    }

    // ---- epilogue: combine warp halves, normalize, out = ctx @ W0 + b0 ----
    __syncthreads();
#pragma unroll
    for (int i = 0; i < 4; i++)                           // W0 -> smem (reuse K area)
        ((float4*)(smem + AT_W0))[i * 256 + tid] = __ldg((const float4*)W0 + i * 256 + tid);

    float* ctxb = (float*)(smem + AT_CTX);
    if (nh == 1) {
#pragma unroll
        for (int mi = 0; mi < 2; mi++)
#pragma unroll
            for (int ni = 0; ni < 8; ni++)
#pragma unroll
                for (int j = 0; j < 4; j++) {
                    int row = mw * 32 + mi * 16 + (j >> 1) * 8 + g;
                    int col = ni * 8 + tq * 2 + (j & 1);
                    ctxb[row * 65 + col] = ctx[mi][ni][j];
                }
    }
    __syncthreads();
    if (nh == 0) {
#pragma unroll
        for (int mi = 0; mi < 2; mi++)
#pragma unroll
            for (int ni = 0; ni < 8; ni++)
#pragma unroll
                for (int j = 0; j < 4; j++) {
                    int row = mw * 32 + mi * 16 + (j >> 1) * 8 + g;
                    int col = ni * 8 + tq * 2 + (j & 1);
                    ctxb[row * 65 + col] = (ctx[mi][ni][j] + ctxb[row * 65 + col]) / lrow[mi][j >> 1];
                }
    }
    __syncthreads();

    const int r = tid >> 1, half = tid & 1;
    const float* b0s = (const float*)(smem + AT_B0);
    const float* w0s = (const float*)(smem + AT_W0);
    float av[32];
#pragma unroll
    for (int i = 0; i < 32; i++) av[i] = b0s[half * 32 + i];
#pragma unroll 4
    for (int e = 0; e < 64; e++) {
        float ce = ctxb[r * 65 + e];
#pragma unroll
        for (int i = 0; i < 32; i++) av[i] += ce * w0s[e * 64 + half * 32 + i];
    }
    float4* op = (float4*)(out + (size_t)(b * SEQ + qb + r) * ED + half * 32);
#pragma unroll
    for (int i = 0; i < 8; i++)
        op[i] = make_float4(av[4 * i], av[4 * i + 1], av[4 * i + 2], av[4 * i + 3]);
}

// ---------------------------------------------------------------------------
extern "C" void kernel_launch(void* const* d_in, const int* in_sizes, int n_in,
                              void* d_out, int out_size)
{
    const float* x  = (const float*)d_in[0];
    const float* Wk = (const float*)d_in[1];
    const float* bk = (const float*)d_in[2];
    const float* Wq = (const float*)d_in[3];
    const float* bq = (const float*)d_in[4];
    const float* Wv = (const float*)d_in[5];
    const float* bv = (const float*)d_in[6];
    const float* W0 = (const float*)d_in[7];
    const float* b0 = (const float*)d_in[8];
    float* out = (float*)d_out;

    cudaFuncSetAttribute(proj_kernel, cudaFuncAttributeMaxDynamicSharedMemorySize, PJ_SMEM);
    cudaFuncSetAttribute(attn_kernel, cudaFuncAttributeMaxDynamicSharedMemorySize, AT_SMEM);

    prep_kernel<<<96, 256>>>(Wq, Wk, Wv);
    proj_kernel<<<dim3(128, 3), 256, PJ_SMEM>>>(x, bq, bk, bv);
    attn_kernel<<<dim3(16, BATCH), 256, AT_SMEM>>>(W0, b0, out);
}

// round 6
// speedup vs baseline: 3.3156x; 1.2402x over previous
#include <cuda_runtime.h>
#include <cuda_bf16.h>
#include <cstdint>

#define BATCH 8
#define SEQ   2048
#define DM    1024
#define ED    64

// ---------------- device scratch (allocation-free rule) ----------------
__device__ __nv_bfloat16 g_qh[BATCH*SEQ*ED], g_ql[BATCH*SEQ*ED];
__device__ __nv_bfloat16 g_kh[BATCH*SEQ*ED], g_kl[BATCH*SEQ*ED];
__device__ __nv_bfloat16 g_vth[BATCH*ED*SEQ], g_vtl[BATCH*ED*SEQ];   // V transposed [b][e][t]
__device__ __nv_bfloat16 g_wth[3*ED*DM],  g_wtl[3*ED*DM];            // W^T [mat][n][d]
// split-K partials: [b][qt][chunk][128][64] fp32 + per-row m/l
__device__ float g_pctx[BATCH*16*4*128*64];
__device__ float g_pm[BATCH*16*4*128];
__device__ float g_pl[BATCH*16*4*128];

// unit table: (qt<<2)|chunk, sorted by chunk size descending (8,6,4,2 tiles)
__constant__ uint8_t c_units[40] = {
    (3<<2)|0,(4<<2)|0,(5<<2)|0,(6<<2)|0,(7<<2)|0,(7<<2)|1,(8<<2)|0,(8<<2)|1,
    (9<<2)|0,(9<<2)|1,(10<<2)|0,(10<<2)|1,(11<<2)|0,(11<<2)|1,(11<<2)|2,
    (12<<2)|0,(12<<2)|1,(12<<2)|2,(13<<2)|0,(13<<2)|1,(13<<2)|2,
    (14<<2)|0,(14<<2)|1,(14<<2)|2,(15<<2)|0,(15<<2)|1,(15<<2)|2,(15<<2)|3,
    (2<<2)|0,(6<<2)|1,(10<<2)|2,(14<<2)|3,
    (1<<2)|0,(5<<2)|1,(9<<2)|2,(13<<2)|3,
    (0<<2)|0,(4<<2)|1,(8<<2)|2,(12<<2)|3
};

// ---------------- helpers ----------------
__device__ __forceinline__ uint32_t smem_u32(const void* p) {
    uint32_t a;
    asm("{ .reg .u64 t; cvta.to.shared.u64 t, %1; cvt.u32.u64 %0, t; }" : "=r"(a) : "l"(p));
    return a;
}
__device__ __forceinline__ void ldmA(uint32_t* a, uint32_t addr) {
    asm volatile("ldmatrix.sync.aligned.m8n8.x4.shared.b16 {%0,%1,%2,%3}, [%4];"
        : "=r"(a[0]), "=r"(a[1]), "=r"(a[2]), "=r"(a[3]) : "r"(addr));
}
__device__ __forceinline__ void ldmB(uint32_t* b, uint32_t addr) {
    asm volatile("ldmatrix.sync.aligned.m8n8.x2.shared.b16 {%0,%1}, [%2];"
        : "=r"(b[0]), "=r"(b[1]) : "r"(addr));
}
__device__ __forceinline__ void mmaf(float* d, const uint32_t* a, const uint32_t* b) {
    asm volatile("mma.sync.aligned.m16n8k16.row.col.f32.bf16.bf16.f32 "
        "{%0,%1,%2,%3}, {%4,%5,%6,%7}, {%8,%9}, {%0,%1,%2,%3};"
        : "+f"(d[0]), "+f"(d[1]), "+f"(d[2]), "+f"(d[3])
        : "r"(a[0]), "r"(a[1]), "r"(a[2]), "r"(a[3]), "r"(b[0]), "r"(b[1]));
}
#define CP16(dst, src)  asm volatile("cp.async.cg.shared.global [%0], [%1], 16;" :: "r"(dst), "l"(src) : "memory")
#define CP_COMMIT()     asm volatile("cp.async.commit_group;" ::: "memory")
#define CP_WAIT0()      asm volatile("cp.async.wait_group 0;" ::: "memory")
#define CP_WAIT1()      asm volatile("cp.async.wait_group 1;" ::: "memory")

union U4 { uint4 u; __nv_bfloat16 h[8]; };
union U2 { uint2 u; __nv_bfloat16 h[4]; };
union UB2 { uint32_t u; __nv_bfloat16 h[2]; };

__device__ __forceinline__ void split2(float f, __nv_bfloat16& hi, __nv_bfloat16& lo) {
    hi = __float2bfloat16(f);
    lo = __float2bfloat16(f - __bfloat162float(hi));
}
__device__ __forceinline__ uint32_t packbf(__nv_bfloat16 a, __nv_bfloat16 b) {
    UB2 u; u.h[0] = a; u.h[1] = b; return u.u;
}

// ---------------------------------------------------------------------------
// Kernel 0: weights -> transposed bf16 hi/lo.
// ---------------------------------------------------------------------------
__global__ void prep_kernel(const float* __restrict__ Wq, const float* __restrict__ Wk,
                            const float* __restrict__ Wv)
{
    int tid = blockIdx.x * 256 + threadIdx.x;
    for (int i = tid; i < 3 * ED * DM; i += 96 * 256) {
        int mat = i >> 16, rem = i & 65535;
        int n = rem >> 10, d = rem & 1023;
        const float* W = (mat == 0) ? Wq : (mat == 1) ? Wk : Wv;
        __nv_bfloat16 h, l;
        split2(W[d * ED + n], h, l);
        g_wth[i] = h; g_wtl[i] = l;
    }
}

// ---------------------------------------------------------------------------
// Kernel 1: QKV projection via mma.sync bf16x3 (W staged via cp.async).
// ---------------------------------------------------------------------------
#define PJ_XH 512
#define PJ_XL 18944
#define PJ_WH 37376
#define PJ_WL 46592
#define PJ_SMEM 55808

__global__ void __launch_bounds__(256, 1)
proj_kernel(const float* __restrict__ x, const float* __restrict__ bq,
            const float* __restrict__ bk, const float* __restrict__ bv)
{
    extern __shared__ char smem[];
    const uint32_t sb = smem_u32(smem);
    const int tid = threadIdx.x, lane = tid & 31, wid = tid >> 5;
    const int mw = wid >> 1, nh = wid & 1;
    const int g = lane >> 2, tq = lane & 3;
    const int mat = blockIdx.y;
    const int rowbase = blockIdx.x * 128;
    const float* bias = (mat == 0) ? bq : (mat == 1) ? bk : bv;
    if (tid < 64) ((float*)smem)[tid] = bias[tid];

    const __nv_bfloat16* wh = g_wth + (size_t)mat * ED * DM;
    const __nv_bfloat16* wl = g_wtl + (size_t)mat * ED * DM;

    float acc[2][4][4];
#pragma unroll
    for (int a = 0; a < 2; a++)
#pragma unroll
        for (int bb = 0; bb < 4; bb++)
#pragma unroll
            for (int c = 0; c < 4; c++) acc[a][bb][c] = 0.0f;

    for (int k0 = 0; k0 < DM; k0 += 64) {
        __syncthreads();
        // W tiles via cp.async, issued first so they overlap X conversion
#pragma unroll
        for (int i = 0; i < 4; i++) {
            int idx = i * 256 + tid;
            int part = idx >> 9, rem = idx & 511;
            int r = rem >> 3, jj = rem & 7;
            const __nv_bfloat16* src = (part ? wl : wh) + (size_t)r * DM + k0;
            CP16(sb + (part ? PJ_WL : PJ_WH) + r * 144 + jj * 16, (const char*)src + jj * 16);
        }
        CP_COMMIT();
#pragma unroll
        for (int i = 0; i < 8; i++) {                    // X tile 128x64 fp32 -> hi/lo
            int idx = i * 256 + tid;
            int r = idx >> 4, jj = idx & 15;
            float4 v = __ldg((const float4*)(x + (size_t)(rowbase + r) * DM + k0) + jj);
            U2 h, l;
            split2(v.x, h.h[0], l.h[0]); split2(v.y, h.h[1], l.h[1]);
            split2(v.z, h.h[2], l.h[2]); split2(v.w, h.h[3], l.h[3]);
            *(uint2*)(smem + PJ_XH + r * 144 + jj * 8) = h.u;
            *(uint2*)(smem + PJ_XL + r * 144 + jj * 8) = l.u;
        }
        CP_WAIT0();
        __syncthreads();

#pragma unroll
        for (int kc = 0; kc < 4; kc++) {
            uint32_t ah[2][4], al[2][4];
#pragma unroll
            for (int mi = 0; mi < 2; mi++) {
                uint32_t ao = (uint32_t)(mw * 32 + mi * 16 + (lane & 15)) * 144 + kc * 32 + (lane >> 4) * 16;
                ldmA(ah[mi], sb + PJ_XH + ao);
                ldmA(al[mi], sb + PJ_XL + ao);
            }
#pragma unroll
            for (int ni = 0; ni < 4; ni++) {
                uint32_t bo = (uint32_t)(nh * 32 + ni * 8 + (lane & 7)) * 144 + kc * 32 + ((lane >> 3) & 1) * 16;
                uint32_t bh[2], bl[2];
                ldmB(bh, sb + PJ_WH + bo);
                ldmB(bl, sb + PJ_WL + bo);
#pragma unroll
                for (int mi = 0; mi < 2; mi++) {
                    mmaf(acc[mi][ni], ah[mi], bh);
                    mmaf(acc[mi][ni], ah[mi], bl);
                    mmaf(acc[mi][ni], al[mi], bh);
                }
            }
        }
    }

    // epilogue: fragments -> staged smem [128][65] -> coalesced hi/lo global stores
    __syncthreads();
    const float scale = (mat == 0) ? 0.125f : 1.0f;
    const float* bs = (const float*)smem;
    float* stg = (float*)(smem + 512);
#pragma unroll
    for (int mi = 0; mi < 2; mi++)
#pragma unroll
        for (int ni = 0; ni < 4; ni++)
#pragma unroll
            for (int j = 0; j < 4; j++) {
                int row = mw * 32 + mi * 16 + (j >> 1) * 8 + g;
                int col = nh * 32 + ni * 8 + tq * 2 + (j & 1);
                stg[row * 65 + col] = (acc[mi][ni][j] + bs[col]) * scale;
            }
    __syncthreads();

    if (mat < 2) {
        int r = tid >> 1, half = tid & 1;
        U4 hb[4], lb[4];
#pragma unroll
        for (int i = 0; i < 32; i++)
            split2(stg[r * 65 + half * 32 + i], hb[i >> 3].h[i & 7], lb[i >> 3].h[i & 7]);
        __nv_bfloat16* dh = ((mat == 0) ? g_qh : g_kh) + (size_t)(rowbase + r) * ED + half * 32;
        __nv_bfloat16* dl = ((mat == 0) ? g_ql : g_kl) + (size_t)(rowbase + r) * ED + half * 32;
#pragma unroll
        for (int i = 0; i < 4; i++) { ((uint4*)dh)[i] = hb[i].u; ((uint4*)dl)[i] = lb[i].u; }
    } else {
        int e = tid >> 2, qq = tid & 3;
        int b = rowbase >> 11, tb = (rowbase & 2047) + qq * 32;
        U4 hb[4], lb[4];
#pragma unroll
        for (int i = 0; i < 32; i++)
            split2(stg[(qq * 32 + i) * 65 + e], hb[i >> 3].h[i & 7], lb[i >> 3].h[i & 7]);
        __nv_bfloat16* dh = g_vth + (size_t)(b * ED + e) * SEQ + tb;
        __nv_bfloat16* dl = g_vtl + (size_t)(b * ED + e) * SEQ + tb;
#pragma unroll
        for (int i = 0; i < 4; i++) { ((uint4*)dh)[i] = hb[i].u; ((uint4*)dl)[i] = lb[i].u; }
    }
}

// ---------------------------------------------------------------------------
// Kernel 2: split-K causal flash attention partials, cp.async double-buffered.
// grid (40, 8) x 256 thr. Unit = (qtile of 128 rows, chunk of <=8 key-tiles).
// SMEM: rmax@0 rsum@1024 QH@2048 QL@20480 KV stages@38912 (2 x 36864).
// Stage layout: KH+0 KL+9216 VH+18432 VL+27648. Total 112640 B.
// Epilogue ctx staging: stride-68 f32 buffer @2048 (Q area, dead after loop).
// ---------------------------------------------------------------------------
#define AT_RMAX 0
#define AT_RSUM 1024
#define AT_QH   2048
#define AT_QL   20480
#define AT_ST   38912
#define AT_STG  36864
#define AT_CTXB 2048
#define AT_SMEM 112640

__global__ void __launch_bounds__(256, 1)
attn_partial(float* __restrict__ dummy)
{
    extern __shared__ char smem[];
    const uint32_t sb = smem_u32(smem);
    const int tid = threadIdx.x, lane = tid & 31, wid = tid >> 5;
    const int mw = wid >> 1, nh = wid & 1;
    const int g = lane >> 2, tq = lane & 3;
    const int b = blockIdx.y;
    const uint32_t u = c_units[blockIdx.x];
    const int qt = u >> 2, ck = u & 3;
    const int qb = qt * 128;
    const int t0 = ck * 8;
    const int t1 = min(t0 + 8, 2 * qt + 2);

    // Q tile hi/lo via cp.async (group 0)
#pragma unroll
    for (int i = 0; i < 8; i++) {
        int idx = i * 256 + tid;
        int part = idx >> 10, rem = idx & 1023;
        int r = rem >> 3, jj = rem & 7;
        const __nv_bfloat16* src = (part ? g_ql : g_qh) + (size_t)(b * SEQ + qb + r) * ED;
        CP16(sb + (part ? AT_QL : AT_QH) + r * 144 + jj * 16, (const char*)src + jj * 16);
    }
    CP_COMMIT();

    // stage K/V tile t into stage s
    auto stage_tile = [&](int t, int s) {
        uint32_t base = sb + AT_ST + s * AT_STG;
#pragma unroll
        for (int i = 0; i < 8; i++) {
            int idx = i * 256 + tid;
            int part = idx >> 9, rem = idx & 511;
            int r = rem >> 3, jj = rem & 7;
            const __nv_bfloat16* src;
            if (part == 0)      src = g_kh  + (size_t)(b * SEQ + t * 64 + r) * ED;
            else if (part == 1) src = g_kl  + (size_t)(b * SEQ + t * 64 + r) * ED;
            else if (part == 2) src = g_vth + (size_t)(b * ED + r) * SEQ + t * 64;
            else                src = g_vtl + (size_t)(b * ED + r) * SEQ + t * 64;
            CP16(base + part * 9216 + r * 144 + jj * 16, (const char*)src + jj * 16);
        }
    };
    stage_tile(t0, 0);
    CP_COMMIT();

    float ctx[2][8][4];
#pragma unroll
    for (int a = 0; a < 2; a++)
#pragma unroll
        for (int bb = 0; bb < 8; bb++)
#pragma unroll
            for (int c = 0; c < 4; c++) ctx[a][bb][c] = 0.0f;
    float mrow[2][2] = {{-1e30f, -1e30f}, {-1e30f, -1e30f}};
    float lrow[2][2] = {{0.0f, 0.0f}, {0.0f, 0.0f}};

    float* rmax = (float*)(smem + AT_RMAX);
    float* rsum = (float*)(smem + AT_RSUM);

    for (int t = t0; t < t1; t++) {
        const int cur = (t - t0) & 1;
        if (t + 1 < t1) { stage_tile(t + 1, cur ^ 1); CP_COMMIT(); CP_WAIT1(); }
        else            { CP_WAIT0(); }
        __syncthreads();
        const uint32_t kb = sb + AT_ST + cur * AT_STG;

        // S = Q K^T
        float s[2][4][4];
#pragma unroll
        for (int a = 0; a < 2; a++)
#pragma unroll
            for (int bb = 0; bb < 4; bb++)
#pragma unroll
                for (int c = 0; c < 4; c++) s[a][bb][c] = 0.0f;

#pragma unroll
        for (int kc = 0; kc < 4; kc++) {
            uint32_t ah[2][4], al[2][4];
#pragma unroll
            for (int mi = 0; mi < 2; mi++) {
                uint32_t ao = (uint32_t)(mw * 32 + mi * 16 + (lane & 15)) * 144 + kc * 32 + (lane >> 4) * 16;
                ldmA(ah[mi], sb + AT_QH + ao);
                ldmA(al[mi], sb + AT_QL + ao);
            }
#pragma unroll
            for (int ni = 0; ni < 4; ni++) {
                uint32_t bo = (uint32_t)(nh * 32 + ni * 8 + (lane & 7)) * 144 + kc * 32 + ((lane >> 3) & 1) * 16;
                uint32_t bh[2], bl[2];
                ldmB(bh, kb + bo);
                ldmB(bl, kb + 9216 + bo);
#pragma unroll
                for (int mi = 0; mi < 2; mi++) {
                    mmaf(s[mi][ni], ah[mi], bh);
                    mmaf(s[mi][ni], ah[mi], bl);
                    mmaf(s[mi][ni], al[mi], bh);
                }
            }
        }

        if (t >= 2 * qt) {                               // causal mask (diagonal tiles)
#pragma unroll
            for (int mi = 0; mi < 2; mi++)
#pragma unroll
                for (int ni = 0; ni < 4; ni++)
#pragma unroll
                    for (int j = 0; j < 4; j++) {
                        int row = qb + mw * 32 + mi * 16 + (j >> 1) * 8 + g;
                        int col = t * 64 + nh * 32 + ni * 8 + tq * 2 + (j & 1);
                        if (col > row) s[mi][ni][j] = -1e30f;
                    }
        }

        // online softmax: quad shuffle + cross-warp smem exchange
        float corr[2][2];
#pragma unroll
        for (int mi = 0; mi < 2; mi++)
#pragma unroll
            for (int rh = 0; rh < 2; rh++) {
                float mx = -1e30f;
#pragma unroll
                for (int ni = 0; ni < 4; ni++)
                    mx = fmaxf(mx, fmaxf(s[mi][ni][rh * 2], s[mi][ni][rh * 2 + 1]));
                mx = fmaxf(mx, __shfl_xor_sync(0xffffffffu, mx, 1));
                mx = fmaxf(mx, __shfl_xor_sync(0xffffffffu, mx, 2));
                if (tq == 0) rmax[(mw * 32 + mi * 16 + rh * 8 + g) * 2 + nh] = mx;
            }
        __syncthreads();
#pragma unroll
        for (int mi = 0; mi < 2; mi++)
#pragma unroll
            for (int rh = 0; rh < 2; rh++) {
                int row = mw * 32 + mi * 16 + rh * 8 + g;
                float tm = fmaxf(rmax[row * 2], rmax[row * 2 + 1]);
                float nm = fmaxf(mrow[mi][rh], tm);
                corr[mi][rh] = __expf(mrow[mi][rh] - nm);
                mrow[mi][rh] = nm;
                float sum = 0.0f;
#pragma unroll
                for (int ni = 0; ni < 4; ni++) {
                    float p0 = __expf(s[mi][ni][rh * 2] - nm);
                    float p1 = __expf(s[mi][ni][rh * 2 + 1] - nm);
                    s[mi][ni][rh * 2] = p0; s[mi][ni][rh * 2 + 1] = p1;
                    sum += p0 + p1;
                }
                sum += __shfl_xor_sync(0xffffffffu, sum, 1);
                sum += __shfl_xor_sync(0xffffffffu, sum, 2);
                if (tq == 0) rsum[row * 2 + nh] = sum;
            }
        __syncthreads();
#pragma unroll
        for (int mi = 0; mi < 2; mi++)
#pragma unroll
            for (int rh = 0; rh < 2; rh++) {
                int row = mw * 32 + mi * 16 + rh * 8 + g;
                lrow[mi][rh] = lrow[mi][rh] * corr[mi][rh] + rsum[row * 2] + rsum[row * 2 + 1];
            }
#pragma unroll
        for (int mi = 0; mi < 2; mi++)
#pragma unroll
            for (int ni = 0; ni < 8; ni++)
#pragma unroll
                for (int j = 0; j < 4; j++) ctx[mi][ni][j] *= corr[mi][j >> 1];

        // PV: P (regs, hi/lo) @ V (smem B-frags)
#pragma unroll
        for (int kc = 0; kc < 2; kc++) {
            uint32_t ph[2][4], pl[2][4];
#pragma unroll
            for (int mi = 0; mi < 2; mi++)
#pragma unroll
                for (int h2 = 0; h2 < 2; h2++)
#pragma unroll
                    for (int rh = 0; rh < 2; rh++) {
                        __nv_bfloat16 h0, l0, h1, l1;
                        split2(s[mi][2 * kc + h2][rh * 2],     h0, l0);
                        split2(s[mi][2 * kc + h2][rh * 2 + 1], h1, l1);
                        ph[mi][h2 * 2 + rh] = packbf(h0, h1);
                        pl[mi][h2 * 2 + rh] = packbf(l0, l1);
                    }
#pragma unroll
            for (int ni = 0; ni < 8; ni++) {
                uint32_t bo = (uint32_t)(ni * 8 + (lane & 7)) * 144 + (nh * 32 + kc * 16) * 2 + ((lane >> 3) & 1) * 16;
                uint32_t bh[2], bl[2];
                ldmB(bh, kb + 18432 + bo);
                ldmB(bl, kb + 27648 + bo);
#pragma unroll
                for (int mi = 0; mi < 2; mi++) {
                    mmaf(ctx[mi][ni], ph[mi], bh);
                    mmaf(ctx[mi][ni], ph[mi], bl);
                    mmaf(ctx[mi][ni], pl[mi], bh);
                }
            }
        }
        __syncthreads();             // done reading stage cur before it is overwritten
    }

    // ---- write partials: combine nh halves (unnormalized) + m/l ----
    float* ctxb = (float*)(smem + AT_CTXB);    // stride 68 floats
    if (nh == 1) {
#pragma unroll
        for (int mi = 0; mi < 2; mi++)
#pragma unroll
            for (int ni = 0; ni < 8; ni++)
#pragma unroll
                for (int j = 0; j < 4; j++) {
                    int row = mw * 32 + mi * 16 + (j >> 1) * 8 + g;
                    int col = ni * 8 + tq * 2 + (j & 1);
                    ctxb[row * 68 + col] = ctx[mi][ni][j];
                }
    }
    __syncthreads();
    if (nh == 0) {
#pragma unroll
        for (int mi = 0; mi < 2; mi++)
#pragma unroll
            for (int ni = 0; ni < 8; ni++)
#pragma unroll
                for (int j = 0; j < 4; j++) {
                    int row = mw * 32 + mi * 16 + (j >> 1) * 8 + g;
                    int col = ni * 8 + tq * 2 + (j & 1);
                    ctxb[row * 68 + col] += ctx[mi][ni][j];
                }
        if (tq == 0) {
            size_t mlb = (size_t)((b * 16 + qt) * 4 + ck) * 128;
#pragma unroll
            for (int mi = 0; mi < 2; mi++)
#pragma unroll
                for (int rh = 0; rh < 2; rh++) {
                    int row = mw * 32 + mi * 16 + rh * 8 + g;
                    g_pm[mlb + row] = mrow[mi][rh];
                    g_pl[mlb + row] = lrow[mi][rh];
                }
        }
    }
    __syncthreads();

    const int r = tid >> 1, half = tid & 1;
    float* dst = g_pctx + ((size_t)((b * 16 + qt) * 4 + ck) << 13) + r * 64 + half * 32;
    const float4* srcf = (const float4*)(ctxb + r * 68 + half * 32);
#pragma unroll
    for (int i = 0; i < 8; i++) ((float4*)dst)[i] = srcf[i];
    (void)dummy;
}

// ---------------------------------------------------------------------------
// Kernel 3: combine partials + output projection. grid (16, 8) x 256 thr.
// SMEM: ctxb[128][65]f32 @0, W0 @33280, b0 @49664. 49920 B.
// ---------------------------------------------------------------------------
#define CB_W0 33280
#define CB_B0 49664
#define CB_SMEM 49920

__global__ void __launch_bounds__(256, 1)
combine_kernel(const float* __restrict__ W0, const float* __restrict__ b0,
               float* __restrict__ out)
{
    extern __shared__ char smem[];
    const int tid = threadIdx.x;
    const int qt = blockIdx.x, b = blockIdx.y;
    const int nchunks = (qt >> 2) + 1;

#pragma unroll
    for (int i = 0; i < 4; i++)
        ((float4*)(smem + CB_W0))[i * 256 + tid] = __ldg((const float4*)W0 + i * 256 + tid);
    if (tid < 64) ((float*)(smem + CB_B0))[tid] = b0[tid];

    const int r = tid >> 1, half = tid & 1;
    const size_t mlb = (size_t)((b * 16 + qt) * 4) * 128 + r;
    float mc[4], lc[4];
    for (int c = 0; c < nchunks; c++) {
        mc[c] = g_pm[mlb + (size_t)c * 128];
        lc[c] = g_pl[mlb + (size_t)c * 128];
    }
    float ms = mc[0];
    for (int c = 1; c < nchunks; c++) ms = fmaxf(ms, mc[c]);
    float ls = 0.0f, wsc[4];
    for (int c = 0; c < nchunks; c++) { wsc[c] = __expf(mc[c] - ms); ls += lc[c] * wsc[c]; }
    const float inv = 1.0f / ls;

    float acc[32];
#pragma unroll
    for (int i = 0; i < 32; i++) acc[i] = 0.0f;
    for (int c = 0; c < nchunks; c++) {
        const float4* p = (const float4*)(g_pctx + ((size_t)((b * 16 + qt) * 4 + c) << 13) + r * 64 + half * 32);
        float w = wsc[c];
#pragma unroll
        for (int i = 0; i < 8; i++) {
            float4 v = p[i];
            acc[4 * i + 0] += v.x * w; acc[4 * i + 1] += v.y * w;
            acc[4 * i + 2] += v.z * w; acc[4 * i + 3] += v.w * w;
        }
    }
    float* ctxb = (float*)smem;
#pragma unroll
    for (int i = 0; i < 32; i++) ctxb[r * 65 + half * 32 + i] = acc[i] * inv;
    __syncthreads();

    const float* b0s = (const float*)(smem + CB_B0);
    const float* w0s = (const float*)(smem + CB_W0);
    float av[32];
#pragma unroll
    for (int i = 0; i < 32; i++) av[i] = b0s[half * 32 + i];
#pragma unroll 4
    for (int e = 0; e < 64; e++) {
        float ce = ctxb[r * 65 + e];
#pragma unroll
        for (int i = 0; i < 32; i++) av[i] += ce * w0s[e * 64 + half * 32 + i];
    }
    float4* op = (float4*)(out + (size_t)(b * SEQ + qt * 128 + r) * ED + half * 32);
#pragma unroll
    for (int i = 0; i < 8; i++)
        op[i] = make_float4(av[4 * i], av[4 * i + 1], av[4 * i + 2], av[4 * i + 3]);
}

// ---------------------------------------------------------------------------
extern "C" void kernel_launch(void* const* d_in, const int* in_sizes, int n_in,
                              void* d_out, int out_size)
{
    const float* x  = (const float*)d_in[0];
    const float* Wk = (const float*)d_in[1];
    const float* bk = (const float*)d_in[2];
    const float* Wq = (const float*)d_in[3];
    const float* bq = (const float*)d_in[4];
    const float* Wv = (const float*)d_in[5];
    const float* bv = (const float*)d_in[6];
    const float* W0 = (const float*)d_in[7];
    const float* b0 = (const float*)d_in[8];
    float* out = (float*)d_out;

    cudaFuncSetAttribute(proj_kernel,    cudaFuncAttributeMaxDynamicSharedMemorySize, PJ_SMEM);
    cudaFuncSetAttribute(attn_partial,   cudaFuncAttributeMaxDynamicSharedMemorySize, AT_SMEM);
    cudaFuncSetAttribute(combine_kernel, cudaFuncAttributeMaxDynamicSharedMemorySize, CB_SMEM);

    prep_kernel<<<96, 256>>>(Wq, Wk, Wv);
    proj_kernel<<<dim3(128, 3), 256, PJ_SMEM>>>(x, bq, bk, bv);
    attn_partial<<<dim3(40, BATCH), 256, AT_SMEM>>>(out);
    combine_kernel<<<dim3(16, BATCH), 256, CB_SMEM>>>(W0, b0, out);
}